// round 4
// baseline (speedup 1.0000x reference)
#include <cuda_runtime.h>
#include <cstdint>

// Problem constants (fixed by the reference)
#define BB 8
#define TT 512
#define DD 512
#define FRAME_BYTES (DD * 4)          // 2048 B per frame
#define MAX_LEN 7680                  // TT * 15
#define PHON_PER_CTA 8
#define NSEG (TT / PHON_PER_CTA)      // 64 CTAs per batch
#define TAIL_PER_CTA (MAX_LEN / NSEG) // 120 tail frames owned per CTA
#define ZBUF_BYTES 8192               // zero staging buffer (4 frames)

// Scratch: per-batch inclusive cumsum of clamped durations (no allocation).
__device__ int g_cum[BB * TT];

// ---------------------------------------------------------------------------
// Kernel 1: inclusive scan of max(dur,1) per batch row.
// shfl warp-scan + 16-partial block scan; only 2 barriers.
// ---------------------------------------------------------------------------
__global__ void __launch_bounds__(TT) scan_kernel(const int* __restrict__ dur) {
    const int b = blockIdx.x, t = threadIdx.x;
    const int lane = t & 31, w = t >> 5;

    int v = dur[b * TT + t];
    v = (v < 1) ? 1 : v;

    int x = v;
#pragma unroll
    for (int o = 1; o < 32; o <<= 1) {
        int y = __shfl_up_sync(0xFFFFFFFFu, x, o);
        if (lane >= o) x += y;
    }
    __shared__ int wsum[16];
    if (lane == 31) wsum[w] = x;
    __syncthreads();
    if (w == 0) {
        int s = (lane < 16) ? wsum[lane] : 0;
#pragma unroll
        for (int o = 1; o < 16; o <<= 1) {
            int y = __shfl_up_sync(0xFFFFFFFFu, s, o);
            if (lane >= o) s += y;
        }
        if (lane < 16) wsum[lane] = s;
    }
    __syncthreads();
    const int base = (w > 0) ? wsum[w - 1] : 0;
    g_cum[b * TT + t] = base + x;
}

// ---------------------------------------------------------------------------
// Kernel 2: bulk-async (TMA) gather-expand.
// Each CTA: batch b, phonemes [t0, t0+8).
//   - stage 16 KB of source frames in SMEM (one-time LDG+STS)
//   - elected thread issues one 2 KB cp.async.bulk store per output repeat
//   - owns tail-zero slice [seg*120, seg*120+120) ∩ [total, MAX_LEN),
//     bulk-stored from a zeroed 8 KB SMEM buffer
// Output bytes never touch L1/LSU; L2 feature re-reads become SMEM re-reads.
// ---------------------------------------------------------------------------
__global__ void __launch_bounds__(128) expand_tma_kernel(
    const float4* __restrict__ feat,  // (B, T, D/4)
    float* __restrict__ out)          // (B, MAX_LEN, D)
{
    __shared__ alignas(128) float4 sframes[PHON_PER_CTA * (DD / 4)]; // 16 KB
    __shared__ alignas(128) float4 szero[ZBUF_BYTES / 16];           //  8 KB

    const int b   = blockIdx.y;
    const int seg = blockIdx.x;               // 0..NSEG-1
    const int t0  = seg * PHON_PER_CTA;
    const int tid = threadIdx.x;              // 0..127

    // Stage 8 frames (16 KB) into SMEM.
    const float4* src = feat + ((size_t)b * TT + t0) * (DD / 4);
#pragma unroll
    for (int i = 0; i < 8; i++)
        sframes[tid + 128 * i] = __ldg(src + tid + 128 * i);
    // Zero staging buffer.
    const float4 z4 = make_float4(0.f, 0.f, 0.f, 0.f);
#pragma unroll
    for (int i = 0; i < 4; i++)
        szero[tid + 128 * i] = z4;
    __syncthreads();

    if (tid == 0) {
        // Order the generic-proxy SMEM writes before async-proxy reads.
        asm volatile("fence.proxy.async.shared::cta;" ::: "memory");

        const int* __restrict__ cum = g_cum + b * TT;
        const int total = cum[TT - 1];
        int prev = (t0 > 0) ? cum[t0 - 1] : 0;

        const uint32_t s_fr = (uint32_t)__cvta_generic_to_shared(sframes);
        const uint32_t s_z  = (uint32_t)__cvta_generic_to_shared(szero);
        char* const outb = (char*)out + (size_t)b * MAX_LEN * FRAME_BYTES;

        // Data stores: one 2 KB bulk store per output repeat.
#pragma unroll
        for (int p = 0; p < PHON_PER_CTA; p++) {
            const int e = cum[t0 + p];
            const uint32_t sp = s_fr + p * FRAME_BYTES;
            for (int r = prev; r < e; r++) {
                char* g = outb + (size_t)r * FRAME_BYTES;
                asm volatile(
                    "cp.async.bulk.global.shared::cta.bulk_group [%0], [%1], %2;"
                    :: "l"(g), "r"(sp), "n"(FRAME_BYTES) : "memory");
            }
            prev = e;
        }

        // Tail zeros: this CTA's slice of [total, MAX_LEN).
        int lo = seg * TAIL_PER_CTA;
        const int hi = lo + TAIL_PER_CTA;
        if (lo < total) lo = total;
        if (hi > lo) {
            size_t nbytes = (size_t)(hi - lo) * FRAME_BYTES;
            char* g = outb + (size_t)lo * FRAME_BYTES;
            while (nbytes > 0) {
                const uint32_t chunk =
                    nbytes > ZBUF_BYTES ? (uint32_t)ZBUF_BYTES : (uint32_t)nbytes;
                asm volatile(
                    "cp.async.bulk.global.shared::cta.bulk_group [%0], [%1], %2;"
                    :: "l"(g), "r"(s_z), "r"(chunk) : "memory");
                g += chunk;
                nbytes -= chunk;
            }
        }

        asm volatile("cp.async.bulk.commit_group;" ::: "memory");
        asm volatile("cp.async.bulk.wait_group 0;" ::: "memory");
    }
    __syncthreads();
}

// ---------------------------------------------------------------------------
// Launch
// ---------------------------------------------------------------------------
extern "C" void kernel_launch(void* const* d_in, const int* in_sizes, int n_in,
                              void* d_out, int out_size) {
    const float4* feat = (const float4*)d_in[0];  // features (8,512,512) f32
    const int*    dur  = (const int*)d_in[1];     // durations (8,512) i32
    float*        out  = (float*)d_out;           // (8,7680,512) f32

    (void)in_sizes; (void)n_in; (void)out_size;

    scan_kernel<<<BB, TT>>>(dur);

    dim3 grid(NSEG, BB, 1);
    expand_tma_kernel<<<grid, 128>>>(feat, out);
}